// round 3
// baseline (speedup 1.0000x reference)
#include <cuda_runtime.h>
#include <cuda_bf16.h>
#include <cstdint>

#define NN 50000
#define EE 100000
#define CC 256
#define NW_WORDS 1568          // ceil(50000/32) node bitmap words (padded)
#define EW_WORDS 3125          // ceil(100000/32) edge bitmap words
#define INF_I 0x7FFFFFFF
#define IDXM 131071            // 2^17-1, EE < 2^17
#define ROUNDS 6

// ---------------- scratch (static device globals; no allocation) -------------
__device__ float g_xt[NN * CC];        // xt = x @ W^T + b
__device__ float g_Wt[CC * CC];
__device__ int   g_deg[NN];
__device__ int   g_off[NN + 1];
__device__ int   g_cur[NN];
__device__ int   g_srclist[EE];
__device__ int   g_mask[NN];

// merge state
__device__ int      g_minFS[NN];
__device__ int      g_minFT[NN];
__device__ int      g_mUS[NN];
__device__ int      g_mUT[NN];
__device__ unsigned g_disc0[NW_WORDS];
__device__ unsigned g_und[EW_WORDS];
__device__ int      g_wl[2][EE];
__device__ int      g_cnt[2];

// ---------------- packed f32x2 helpers ---------------------------------------
__device__ __forceinline__ unsigned long long pack2(float x, float y) {
    unsigned long long r;
    asm("mov.b64 %0, {%1, %2};" : "=l"(r) : "f"(x), "f"(y));
    return r;
}
__device__ __forceinline__ void unpack2(unsigned long long p, float& x, float& y) {
    asm("mov.b64 {%0, %1}, %2;" : "=f"(x), "=f"(y) : "l"(p));
}
#define FMA2(d, a, b) asm("fma.rn.f32x2 %0, %1, %2, %0;" : "+l"(d) : "l"(a), "l"(b))

// ---------------- fused init + W transpose -----------------------------------
__global__ void init_prep_kernel(const float* __restrict__ W) {
    int i = blockIdx.x * blockDim.x + threadIdx.x;
    if (i < NN) {
        g_minFS[i] = INF_I;
        g_minFT[i] = INF_I;
        g_mUS[i] = 0;
        g_mUT[i] = 0;
        g_deg[i] = 0;
    }
    if (i < NW_WORDS) g_disc0[i] = 0u;
    if (i < EW_WORDS) g_und[i] = 0u;
    if (i == 0) { g_cnt[0] = 0; g_cnt[1] = 0; }
    if (i < CC * CC) {
        int j = i >> 8, k = i & 255;
        g_Wt[k * CC + j] = W[i];        // W[j][k] -> Wt[k][j]
    }
}

// ---------------- GEMM: xt = x @ W^T + b  (FFMA2, 128x256 tile, 8x16/thread) -
__global__ __launch_bounds__(256, 1)
void gemm_kernel(const float* __restrict__ x, const float* __restrict__ bias, int M) {
    __shared__ float As[2][8][128];
    __shared__ float Bs[2][8][256];

    const int tid = threadIdx.x;
    const int m0 = blockIdx.x * 128;
    const int tr = tid >> 4;        // 0..15 -> rows tr*8 .. tr*8+7
    const int tc = tid & 15;        // 0..15 -> cols { p*64 + tc*4 + (0..3), p=0..3 }

    // A gmem load: row = tid>>1 (0..127), col4 = (tid&1)*4
    const int ar = tid >> 1, ac = (tid & 1) * 4;
    // B gmem load: row = tid>>5 (0..7), cols (tid&31)*4 and +128
    const int br = tid >> 5, bc = (tid & 31) * 4;

    int arow = m0 + ar;
    if (arow >= M) arow = M - 1;    // clamp; stores are guarded

    // prefetch tile 0
    float4 av  = *reinterpret_cast<const float4*>(x + (size_t)arow * CC + ac);
    float4 bv0 = *reinterpret_cast<const float4*>(g_Wt + (size_t)br * CC + bc);
    float4 bv1 = *reinterpret_cast<const float4*>(g_Wt + (size_t)br * CC + bc + 128);

    unsigned long long acc[8][8];   // [i][2p + half] -> rows tr*8+i, cols p*64+tc*4+{0,1 | 2,3}
#pragma unroll
    for (int i = 0; i < 8; i++)
#pragma unroll
        for (int j = 0; j < 8; j++) acc[i][j] = 0ULL;

    int buf = 0;
    for (int k0 = 0; k0 < CC; k0 += 8) {
        // commit prefetched tile to smem[buf]
        As[buf][ac + 0][ar] = av.x;
        As[buf][ac + 1][ar] = av.y;
        As[buf][ac + 2][ar] = av.z;
        As[buf][ac + 3][ar] = av.w;
        *reinterpret_cast<float4*>(&Bs[buf][br][bc])       = bv0;
        *reinterpret_cast<float4*>(&Bs[buf][br][bc + 128]) = bv1;
        __syncthreads();

        if (k0 + 8 < CC) {
            av  = *reinterpret_cast<const float4*>(x + (size_t)arow * CC + k0 + 8 + ac);
            bv0 = *reinterpret_cast<const float4*>(g_Wt + (size_t)(k0 + 8 + br) * CC + bc);
            bv1 = *reinterpret_cast<const float4*>(g_Wt + (size_t)(k0 + 8 + br) * CC + bc + 128);
        }

#pragma unroll
        for (int kk = 0; kk < 8; kk++) {
            float4 a0 = *reinterpret_cast<float4*>(&As[buf][kk][tr * 8]);
            float4 a1 = *reinterpret_cast<float4*>(&As[buf][kk][tr * 8 + 4]);
            unsigned long long ap[8];
            ap[0] = pack2(a0.x, a0.x); ap[1] = pack2(a0.y, a0.y);
            ap[2] = pack2(a0.z, a0.z); ap[3] = pack2(a0.w, a0.w);
            ap[4] = pack2(a1.x, a1.x); ap[5] = pack2(a1.y, a1.y);
            ap[6] = pack2(a1.z, a1.z); ap[7] = pack2(a1.w, a1.w);

            unsigned long long bp[8];
#pragma unroll
            for (int p = 0; p < 4; p++) {
                float4 q = *reinterpret_cast<float4*>(&Bs[buf][kk][p * 64 + tc * 4]);
                bp[2 * p]     = pack2(q.x, q.y);
                bp[2 * p + 1] = pack2(q.z, q.w);
            }
#pragma unroll
            for (int i = 0; i < 8; i++)
#pragma unroll
                for (int j = 0; j < 8; j++)
                    FMA2(acc[i][j], ap[i], bp[j]);
        }
        buf ^= 1;
        __syncthreads();
    }

    float4 b4[4];
#pragma unroll
    for (int p = 0; p < 4; p++)
        b4[p] = *reinterpret_cast<const float4*>(bias + p * 64 + tc * 4);

#pragma unroll
    for (int i = 0; i < 8; i++) {
        int row = m0 + tr * 8 + i;
        if (row < M) {
#pragma unroll
            for (int p = 0; p < 4; p++) {
                float v0, v1, v2, v3;
                unpack2(acc[i][2 * p],     v0, v1);
                unpack2(acc[i][2 * p + 1], v2, v3);
                float4 o = make_float4(v0 + b4[p].x, v1 + b4[p].y,
                                       v2 + b4[p].z, v3 + b4[p].w);
                *reinterpret_cast<float4*>(g_xt + (size_t)row * CC + p * 64 + tc * 4) = o;
            }
        }
    }
}

// ---------------- disc0 bitmap + degree count (fused) -------------------------
__global__ void disc_deg_kernel(const int* __restrict__ ei) {
    int e = blockIdx.x * blockDim.x + threadIdx.x;
    if (e < EE) {
        int s = ei[e];
        int t = ei[EE + e];
        atomicOr(&g_disc0[s >> 5], 1u << (s & 31));
        atomicAdd(&g_deg[t], 1);
    }
}

// ---------------- build initial worklist (static base filter) ----------------
__global__ void build_kernel(const int* __restrict__ ei) {
    int e = blockIdx.x * blockDim.x + threadIdx.x;
    if (e < EE) {
        int s = ei[e];
        int t = ei[EE + e];
        bool base = (s != t) && ((g_disc0[t >> 5] >> (t & 31)) & 1u);
        if (base) {
            int pos = atomicAdd(&g_cnt[0], 1);
            g_wl[0][pos] = e;
            atomicOr(&g_und[e >> 5], 1u << (e & 31));
        }
    }
}

// ---------------- round pass A: stamp per-node min undecided index -----------
__global__ void stampA_kernel(const int* __restrict__ ei, int round) {
    int cur = (round - 1) & 1, nxt = round & 1;
    if (blockIdx.x == 0 && threadIdx.x == 0) g_cnt[nxt] = 0;
    int n = g_cnt[cur];
    int idx = blockIdx.x * blockDim.x + threadIdx.x;
    if (idx >= n) return;
    int e = g_wl[cur][idx];
    int s = ei[e], t = ei[EE + e];
    int key = (round << 17) | (IDXM - e);
    atomicMax(&g_mUS[s], key);
    atomicMax(&g_mUT[t], key);
}

__device__ __forceinline__ int decode_stamp(int key, int round) {
    return ((key >> 17) == round) ? (IDXM - (key & IDXM)) : INF_I;
}

// ---------------- round pass B: decide fire/die/stay --------------------------
__global__ void decideB_kernel(const int* __restrict__ ei, int round) {
    int cur = (round - 1) & 1, nxt = round & 1;
    int n = g_cnt[cur];
    int idx = blockIdx.x * blockDim.x + threadIdx.x;
    if (idx >= n) return;
    int e = g_wl[cur][idx];
    int s = ei[e], t = ei[EE + e];

    bool killed = (g_minFS[s] < e) || (g_minFS[t] < e) || (g_minFT[t] < e);
    bool decided;
    if (!killed) {
        int a = decode_stamp(g_mUS[s], round);
        int c = decode_stamp(g_mUS[t], round);
        int d = decode_stamp(g_mUT[t], round);
        if (a >= e && c >= e && d >= e) {
            atomicMin(&g_minFS[s], e);
            atomicMin(&g_minFT[t], e);
            decided = true;
        } else {
            int pos = atomicAdd(&g_cnt[nxt], 1);
            g_wl[nxt][pos] = e;
            decided = false;
        }
    } else {
        decided = true;
    }
    if (decided) atomicAnd(&g_und[e >> 5], ~(1u << (e & 31)));
}

// ---------------- sequential finisher (1 warp, exact index order) ------------
__global__ __launch_bounds__(32, 1)
void finish_kernel(const int* __restrict__ ei) {
    __shared__ int sS[32];
    __shared__ int sT[32];
    const unsigned FULL = 0xFFFFFFFFu;
    const int lane = threadIdx.x;

    for (int w0 = 0; w0 < EW_WORDS; w0 += 32) {
        int w = w0 + lane;
        unsigned word = (w < EW_WORDS) ? __ldcg(&g_und[w]) : 0u;
        unsigned nz = __ballot_sync(FULL, word != 0u);
        while (nz) {
            int j = __ffs(nz) - 1;
            nz &= nz - 1;
            unsigned ww = __shfl_sync(FULL, word, j);
            int wi = w0 + j;
            int i = wi * 32 + lane;
            bool valid = ((ww >> lane) & 1u) != 0u;
            int s = 0, t = 0;
            if (valid) { s = __ldg(&ei[i]); t = __ldg(&ei[EE + i]); }
            bool cand = false;
            if (valid) {
                bool killed = (__ldcg(&g_minFS[s]) < i) ||
                              (__ldcg(&g_minFS[t]) < i) ||
                              (__ldcg(&g_minFT[t]) < i);
                cand = !killed;
            }
            sS[lane] = s;
            sT[lane] = t;
            __syncwarp(FULL);
            unsigned candm = __ballot_sync(FULL, cand);
            if (candm) {
                unsigned conflict = 0;
#pragma unroll
                for (int q = 0; q < 32; q++) {
                    if (q < lane && ((candm >> q) & 1u)) {
                        int sq = sS[q], tq = sT[q];
                        if (sq == s || sq == t || tq == t) conflict |= (1u << q);
                    }
                }
                unsigned fired = 0;
                unsigned decidedm = ~candm;
                while (decidedm != FULL) {
                    bool undec = !((decidedm >> lane) & 1u);
                    bool ready = undec && ((conflict & ~decidedm) == 0u);
                    bool f = ready && ((conflict & fired) == 0u);
                    decidedm |= __ballot_sync(FULL, ready);
                    fired    |= __ballot_sync(FULL, f);
                }
                if ((fired >> lane) & 1u) {
                    atomicMin(&g_minFS[s], i);
                    atomicMin(&g_minFT[t], i);
                }
                __threadfence();
            }
            __syncwarp(FULL);
        }
    }
}

// ---------------- scan (single block) + mask ---------------------------------
__global__ __launch_bounds__(1024, 1)
void scan_kernel() {
    __shared__ int wsums[32];
    const int tid = threadIdx.x;

    // mask: node kept iff never fired as a source
    for (int v = tid; v < NN; v += 1024)
        g_mask[v] = (g_minFS[v] == INF_I) ? 1 : 0;

    const int PER = 49;
    const int start = tid * PER;

    int s = 0;
    for (int i = 0; i < PER; i++) {
        int idx = start + i;
        if (idx < NN) s += g_deg[idx];
    }
    int lane = tid & 31, wid = tid >> 5;
    int v = s;
#pragma unroll
    for (int o = 1; o < 32; o <<= 1) {
        int n = __shfl_up_sync(0xFFFFFFFFu, v, o);
        if (lane >= o) v += n;
    }
    if (lane == 31) wsums[wid] = v;
    __syncthreads();
    if (wid == 0) {
        int w = wsums[lane];
#pragma unroll
        for (int o = 1; o < 32; o <<= 1) {
            int n = __shfl_up_sync(0xFFFFFFFFu, w, o);
            if (lane >= o) w += n;
        }
        wsums[lane] = w;
    }
    __syncthreads();
    int excl = v - s + (wid > 0 ? wsums[wid - 1] : 0);
    int off = excl;
    for (int i = 0; i < PER; i++) {
        int idx = start + i;
        if (idx < NN) {
            int d = g_deg[idx];
            g_off[idx] = off;
            g_cur[idx] = off;
            off += d;
        }
    }
    if (tid == 1023) g_off[NN] = off;
}

// ---------------- CSR fill ---------------------------------------------------
__global__ void fill_kernel(const int* __restrict__ ei) {
    int e = blockIdx.x * blockDim.x + threadIdx.x;
    if (e < EE) {
        int dst = ei[EE + e];
        int p = atomicAdd(&g_cur[dst], 1);
        g_srclist[p] = ei[e];
    }
}

// ---------------- gather-mean + mask + output (1 warp per node) --------------
__global__ __launch_bounds__(256, 8)
void out_kernel(float* __restrict__ out) {
    int warp = (blockIdx.x * blockDim.x + threadIdx.x) >> 5;
    int lane = threadIdx.x & 31;
    if (warp >= NN) return;
    const int v = warp;

    float4* o = reinterpret_cast<float4*>(out + (size_t)v * CC);
    if (!g_mask[v]) {
        o[lane]      = make_float4(0.f, 0.f, 0.f, 0.f);
        o[lane + 32] = make_float4(0.f, 0.f, 0.f, 0.f);
        return;
    }
    const float4* xv = reinterpret_cast<const float4*>(g_xt + (size_t)v * CC);
    float4 a0 = xv[lane];
    float4 a1 = xv[lane + 32];
    int s0 = g_off[v], s1 = g_off[v + 1];
    for (int j = s0; j < s1; j++) {
        int u = g_srclist[j];
        const float4* p = reinterpret_cast<const float4*>(g_xt + (size_t)u * CC);
        float4 q0 = p[lane];
        float4 q1 = p[lane + 32];
        a0.x += q0.x; a0.y += q0.y; a0.z += q0.z; a0.w += q0.w;
        a1.x += q1.x; a1.y += q1.y; a1.z += q1.z; a1.w += q1.w;
    }
    float inv = 1.f / (float)(s1 - s0 + 1);
    a0.x *= inv; a0.y *= inv; a0.z *= inv; a0.w *= inv;
    a1.x *= inv; a1.y *= inv; a1.z *= inv; a1.w *= inv;
    o[lane]      = a0;
    o[lane + 32] = a1;
}

// ---------------- tail: write mask (as float) + zero any padding -------------
__global__ void tail_kernel(float* __restrict__ out, int out_size) {
    int i = blockIdx.x * blockDim.x + threadIdx.x;
    int idx = NN * CC + i;
    if (idx < out_size)
        out[idx] = (i < NN) ? (float)g_mask[i] : 0.f;
}

// ---------------- launch -----------------------------------------------------
extern "C" void kernel_launch(void* const* d_in, const int* in_sizes, int n_in,
                              void* d_out, int out_size) {
    const float* x  = (const float*)d_in[0];
    const int*   ei = (const int*)d_in[1];
    const float* W  = (const float*)d_in[2];
    const float* b  = (const float*)d_in[3];
    float* out = (float*)d_out;

    const int M = in_sizes[0] / CC;   // 50000

    init_prep_kernel<<<(CC * CC + 255) / 256, 256>>>(W);
    gemm_kernel<<<(M + 127) / 128, 256>>>(x, b, M);

    disc_deg_kernel<<<(EE + 255) / 256, 256>>>(ei);
    build_kernel<<<(EE + 255) / 256, 256>>>(ei);

    for (int r = 1; r <= ROUNDS; r++) {
        stampA_kernel<<<(EE + 255) / 256, 256>>>(ei, r);
        decideB_kernel<<<(EE + 255) / 256, 256>>>(ei, r);
    }
    finish_kernel<<<1, 32>>>(ei);

    scan_kernel<<<1, 1024>>>();
    fill_kernel<<<(EE + 255) / 256, 256>>>(ei);
    out_kernel<<<(NN * 32 + 255) / 256, 256>>>(out);

    int tail = out_size - NN * CC;
    if (tail > 0)
        tail_kernel<<<(tail + 255) / 256, 256>>>(out, out_size);
}